// round 12
// baseline (speedup 1.0000x reference)
#include <cuda_runtime.h>
#include <cuda_bf16.h>
#include <cstdint>
#include <cmath>

#define NG    8192
#define BGRP  16
#define GS    512
#define DIM   768

// tile sizes (proven config)
#define TBM 128
#define TBN 128
#define TBK 64
#define NSTAGE 3
#define STAGE_ELEMS (TBM * TBK)                   // 8192 bf16 per operand per stage
#define SMEM_BYTES (NSTAGE * 2 * STAGE_ELEMS * 2) // 98304 bytes

// ---------------- scratch (device globals; no allocs allowed) ----------------
__device__ __nv_bfloat16 g_xb [NG * DIM];
__device__ __nv_bfloat16 g_Wqb[DIM * DIM];
__device__ __nv_bfloat16 g_Wkb[DIM * DIM];
__device__ __nv_bfloat16 g_Wvb[DIM * DIM];
__device__ __nv_bfloat16 g_Wob[DIM * DIM];
__device__ __nv_bfloat16 g_Q  [NG * DIM];
__device__ __nv_bfloat16 g_K  [NG * DIM];
__device__ __nv_bfloat16 g_V  [NG * DIM];
__device__ float         g_S  [BGRP * GS * GS];
__device__ __nv_bfloat16 g_P  [BGRP * GS * GS];
__device__ __nv_bfloat16 g_DYN[NG * DIM];

// ---------------- helpers ----------------
__device__ __forceinline__ unsigned sptr(const void* p) {
    return (unsigned)__cvta_generic_to_shared(p);
}
__device__ __forceinline__ void cpasync16(unsigned s, const void* g) {
    asm volatile("cp.async.cg.shared.global [%0], [%1], 16;\n" :: "r"(s), "l"(g));
}
__device__ __forceinline__ void cp_commit() {
    asm volatile("cp.async.commit_group;\n" ::: "memory");
}
__device__ __forceinline__ void cp_wait1() {
    asm volatile("cp.async.wait_group 1;\n" ::: "memory");
}
__device__ __forceinline__ void ldsm4(unsigned& r0, unsigned& r1, unsigned& r2, unsigned& r3, unsigned a) {
    asm volatile("ldmatrix.sync.aligned.m8n8.x4.shared.b16 {%0,%1,%2,%3}, [%4];\n"
                 : "=r"(r0), "=r"(r1), "=r"(r2), "=r"(r3) : "r"(a));
}
__device__ __forceinline__ void ldsm4t(unsigned& r0, unsigned& r1, unsigned& r2, unsigned& r3, unsigned a) {
    asm volatile("ldmatrix.sync.aligned.m8n8.x4.trans.shared.b16 {%0,%1,%2,%3}, [%4];\n"
                 : "=r"(r0), "=r"(r1), "=r"(r2), "=r"(r3) : "r"(a));
}
__device__ __forceinline__ void mma16816(float* d, const unsigned* a, const unsigned* b) {
    asm volatile(
        "mma.sync.aligned.m16n8k16.row.col.f32.bf16.bf16.f32 "
        "{%0,%1,%2,%3}, {%4,%5,%6,%7}, {%8,%9}, {%0,%1,%2,%3};\n"
        : "+f"(d[0]), "+f"(d[1]), "+f"(d[2]), "+f"(d[3])
        : "r"(a[0]), "r"(a[1]), "r"(a[2]), "r"(a[3]), "r"(b[0]), "r"(b[1]));
}

// ---- cp.async tile issue into stage buffers (BK=64 -> 128B rows, 8-way XOR swizzle) ----
template<bool TB>
__device__ __forceinline__ void issue_tile(
    const __nv_bfloat16* __restrict__ A, const __nv_bfloat16* __restrict__ B,
    __nv_bfloat16* As, __nv_bfloat16* Bs,
    int row0, int col0, int lda, int ldb, int kt, int tid)
{
#pragma unroll
    for (int i = 0; i < 4; i++) {
        int lin = tid + i * 256;
        int r = lin >> 3, c = lin & 7;
        const __nv_bfloat16* g = A + (long)(row0 + r) * lda + kt * TBK + c * 8;
        cpasync16(sptr(As + r * TBK + ((c ^ (r & 7)) << 3)), g);
    }
    if (!TB) {
#pragma unroll
        for (int i = 0; i < 4; i++) {
            int lin = tid + i * 256;
            int r = lin >> 3, c = lin & 7;
            const __nv_bfloat16* g = B + (long)(col0 + r) * ldb + kt * TBK + c * 8;
            cpasync16(sptr(Bs + r * TBK + ((c ^ (r & 7)) << 3)), g);
        }
    } else {
#pragma unroll
        for (int i = 0; i < 4; i++) {
            int lin = tid + i * 256;
            int r = lin >> 4, c = lin & 15;
            const __nv_bfloat16* g = B + (long)(kt * TBK + r) * ldb + col0 + c * 8;
            cpasync16(sptr(Bs + r * TBN + ((c ^ (r & 7)) << 3)), g);
        }
    }
}

// ---------------------------------------------------------------------------
// Core bf16 tensor-core GEMM body (single-barrier 3-stage pipeline).
// MODE 0: bf16 C = acc + bias[col]
// MODE 1: fp32 C = acc
// MODE 2: bf16 C = acc
// MODE 3: fp32 C = X + beta[0]*(acc + bias[col])
// ---------------------------------------------------------------------------
template<int MODE, bool TB>
__device__ __forceinline__ void gemm_body(
    const __nv_bfloat16* __restrict__ A, const __nv_bfloat16* __restrict__ B,
    const float* __restrict__ bias, void* __restrict__ Cv,
    int K, int lda, int ldb, int ldc,
    const float* __restrict__ X, const float* __restrict__ beta,
    char* dsm, int row0, int col0)
{
    __nv_bfloat16* As = reinterpret_cast<__nv_bfloat16*>(dsm);
    __nv_bfloat16* Bs = As + NSTAGE * STAGE_ELEMS;

    const int tid  = threadIdx.x;
    const int lane = tid & 31;
    const int wid  = tid >> 5;
    const int wm   = (wid & 1) * 64;
    const int wn   = (wid >> 1) * 32;

    float acc[4][4][4];
#pragma unroll
    for (int i = 0; i < 4; i++)
#pragma unroll
        for (int j = 0; j < 4; j++)
#pragma unroll
            for (int k = 0; k < 4; k++) acc[i][j][k] = 0.f;

    const int ntiles = K / TBK;

    issue_tile<TB>(A, B, As, Bs, row0, col0, lda, ldb, 0, tid);
    cp_commit();
    issue_tile<TB>(A, B, As + STAGE_ELEMS, Bs + STAGE_ELEMS, row0, col0, lda, ldb, 1, tid);
    cp_commit();

    for (int kt = 0; kt < ntiles; kt++) {
        const int stg = kt % NSTAGE;
        cp_wait1();
        __syncthreads();

        const __nv_bfloat16* Asb = As + stg * STAGE_ELEMS;
        const __nv_bfloat16* Bsb = Bs + stg * STAGE_ELEMS;

#pragma unroll
        for (int ks = 0; ks < 4; ks++) {
            unsigned aF[4][4], bF[4][2];
#pragma unroll
            for (int mi = 0; mi < 4; mi++) {
                int r = wm + mi * 16 + (lane & 15);
                int c = ks * 2 + (lane >> 4);
                ldsm4(aF[mi][0], aF[mi][1], aF[mi][2], aF[mi][3],
                      sptr(Asb + r * TBK + ((c ^ (r & 7)) << 3)));
            }
            if (!TB) {
#pragma unroll
                for (int nt = 0; nt < 2; nt++) {
                    int r = wn + nt * 16 + (lane & 15);
                    int c = ks * 2 + (lane >> 4);
                    unsigned r0, r1, r2, r3;
                    ldsm4(r0, r1, r2, r3,
                          sptr(Bsb + r * TBK + ((c ^ (r & 7)) << 3)));
                    bF[nt * 2 + 0][0] = r0; bF[nt * 2 + 0][1] = r2;
                    bF[nt * 2 + 1][0] = r1; bF[nt * 2 + 1][1] = r3;
                }
            } else {
#pragma unroll
                for (int nt = 0; nt < 2; nt++) {
                    int r = ks * 16 + (lane & 15);
                    int c = (wn >> 3) + nt * 2 + (lane >> 4);
                    unsigned r0, r1, r2, r3;
                    ldsm4t(r0, r1, r2, r3,
                           sptr(Bsb + r * TBN + ((c ^ (r & 7)) << 3)));
                    bF[nt * 2 + 0][0] = r0; bF[nt * 2 + 0][1] = r1;
                    bF[nt * 2 + 1][0] = r2; bF[nt * 2 + 1][1] = r3;
                }
            }
#pragma unroll
            for (int mi = 0; mi < 4; mi++)
#pragma unroll
                for (int nj = 0; nj < 4; nj++)
                    mma16816(acc[mi][nj], aF[mi], bF[nj]);
        }

        if (kt + 2 < ntiles) {
            const int ps = (kt + 2) % NSTAGE;
            issue_tile<TB>(A, B, As + ps * STAGE_ELEMS, Bs + ps * STAGE_ELEMS,
                           row0, col0, lda, ldb, kt + 2, tid);
        }
        cp_commit();
    }

    // ---------------- epilogue ----------------
    const int rg = lane >> 2;
    const int t  = lane & 3;
    float betav = 0.f;
    if (MODE == 3) betav = beta[0];

#pragma unroll
    for (int mi = 0; mi < 4; mi++) {
#pragma unroll
        for (int nj = 0; nj < 4; nj++) {
            const int r = row0 + wm + mi * 16 + rg;
            const int c = col0 + wn + nj * 8 + t * 2;
            const float d0 = acc[mi][nj][0];
            const float d1 = acc[mi][nj][1];
            const float d2 = acc[mi][nj][2];
            const float d3 = acc[mi][nj][3];

            if (MODE == 0) {
                __nv_bfloat16* C = reinterpret_cast<__nv_bfloat16*>(Cv);
                const float2 bb = *reinterpret_cast<const float2*>(bias + c);
                *reinterpret_cast<__nv_bfloat162*>(C + (long)r * ldc + c) =
                    __floats2bfloat162_rn(d0 + bb.x, d1 + bb.y);
                *reinterpret_cast<__nv_bfloat162*>(C + (long)(r + 8) * ldc + c) =
                    __floats2bfloat162_rn(d2 + bb.x, d3 + bb.y);
            } else if (MODE == 1) {
                float* C = reinterpret_cast<float*>(Cv);
                *reinterpret_cast<float2*>(C + (long)r * ldc + c) = make_float2(d0, d1);
                *reinterpret_cast<float2*>(C + (long)(r + 8) * ldc + c) = make_float2(d2, d3);
            } else if (MODE == 2) {
                __nv_bfloat16* C = reinterpret_cast<__nv_bfloat16*>(Cv);
                *reinterpret_cast<__nv_bfloat162*>(C + (long)r * ldc + c) =
                    __floats2bfloat162_rn(d0, d1);
                *reinterpret_cast<__nv_bfloat162*>(C + (long)(r + 8) * ldc + c) =
                    __floats2bfloat162_rn(d2, d3);
            } else {
                float* C = reinterpret_cast<float*>(Cv);
                const float2 bb = *reinterpret_cast<const float2*>(bias + c);
                const float2 x0 = *reinterpret_cast<const float2*>(X + (long)r * ldc + c);
                const float2 x1 = *reinterpret_cast<const float2*>(X + (long)(r + 8) * ldc + c);
                *reinterpret_cast<float2*>(C + (long)r * ldc + c) =
                    make_float2(x0.x + betav * (d0 + bb.x), x0.y + betav * (d1 + bb.y));
                *reinterpret_cast<float2*>(C + (long)(r + 8) * ldc + c) =
                    make_float2(x1.x + betav * (d2 + bb.x), x1.y + betav * (d3 + bb.y));
            }
        }
    }
}

// ---------------- Q/K fused: grid.z in {0,1} selects W/bias/C ----------------
__global__ __launch_bounds__(256, 2)
void hgemm_qk(const __nv_bfloat16* __restrict__ A,
              const __nv_bfloat16* __restrict__ W0, const __nv_bfloat16* __restrict__ W1,
              const float* __restrict__ b0, const float* __restrict__ b1,
              __nv_bfloat16* __restrict__ C0, __nv_bfloat16* __restrict__ C1)
{
    extern __shared__ char dsm[];
    const int z = blockIdx.z;
    const __nv_bfloat16* W = (z == 0) ? W0 : W1;
    const float* bias      = (z == 0) ? b0 : b1;
    __nv_bfloat16* C       = (z == 0) ? C0 : C1;
    gemm_body<0, false>(A, W, bias, C, DIM, DIM, DIM, DIM, nullptr, nullptr,
                        dsm, blockIdx.y * TBM, blockIdx.x * TBN);
}

// ---------------- generic batched GEMM (z = group) ----------------
template<int MODE, bool TB>
__global__ __launch_bounds__(256, 2)
void hgemm(const __nv_bfloat16* __restrict__ A, const __nv_bfloat16* __restrict__ B,
           const float* __restrict__ bias, void* __restrict__ Cv,
           int K, int lda, int ldb, int ldc,
           long sA, long sB, long sC,
           const float* __restrict__ X, const float* __restrict__ beta)
{
    extern __shared__ char dsm[];
    const int bz = blockIdx.z;
    void* C;
    if (MODE == 1 || MODE == 3) C = (void*)((float*)Cv + bz * sC);
    else                        C = (void*)((__nv_bfloat16*)Cv + bz * sC);
    gemm_body<MODE, TB>(A + bz * sA, B + bz * sB, bias, C,
                        K, lda, ldb, ldc, X, beta,
                        dsm, blockIdx.y * TBM, blockIdx.x * TBN);
}

// ---------------- merged fp32 -> bf16 converts ----------------
__global__ __launch_bounds__(256)
void conv_all(const float* __restrict__ x,
              const float* __restrict__ wq, const float* __restrict__ wk,
              const float* __restrict__ wv, const float* __restrict__ wo,
              __nv_bfloat16* __restrict__ xb,
              __nv_bfloat16* __restrict__ wqb, __nv_bfloat16* __restrict__ wkb,
              __nv_bfloat16* __restrict__ wvb, __nv_bfloat16* __restrict__ wob)
{
    const long NX = (long)NG * DIM;
    const long W  = (long)DIM * DIM;
    long i = ((long)blockIdx.x * 256 + threadIdx.x) * 4;
    if (i >= NX + 4 * W) return;
    const float* src;
    __nv_bfloat16* dst;
    long off;
    if (i < NX) { src = x; dst = xb; off = i; }
    else {
        long j = i - NX;
        int w = (int)(j / W);
        off = j - (long)w * W;
        src = (w == 0) ? wq : (w == 1) ? wk : (w == 2) ? wv : wo;
        dst = (w == 0) ? wqb : (w == 1) ? wkb : (w == 2) ? wvb : wob;
    }
    float4 v = *reinterpret_cast<const float4*>(src + off);
    *reinterpret_cast<__nv_bfloat162*>(dst + off)     = __floats2bfloat162_rn(v.x, v.y);
    *reinterpret_cast<__nv_bfloat162*>(dst + off + 2) = __floats2bfloat162_rn(v.z, v.w);
}

// ---------------- masked softmax (scale folded), warp-per-row ----------------
__global__ __launch_bounds__(256)
void softmax_rows(const float* __restrict__ S, __nv_bfloat16* __restrict__ P, float scale)
{
    const int row  = blockIdx.x * 8 + (threadIdx.x >> 5);
    const int lane = threadIdx.x & 31;
    const int grp  = row >> 9;
    const int r    = row & 511;
    const float* p = S + ((long)grp << 18) + ((long)r << 9);
    __nv_bfloat16* q = P + ((long)grp << 18) + ((long)r << 9);

    float v[16];
    float mx = -INFINITY;
#pragma unroll
    for (int i = 0; i < 4; i++) {
        const int col = i * 128 + lane * 4;
        float4 v4 = *reinterpret_cast<const float4*>(p + col);
        v[i * 4 + 0] = (col + 0 == r) ? -INFINITY : v4.x * scale;
        v[i * 4 + 1] = (col + 1 == r) ? -INFINITY : v4.y * scale;
        v[i * 4 + 2] = (col + 2 == r) ? -INFINITY : v4.z * scale;
        v[i * 4 + 3] = (col + 3 == r) ? -INFINITY : v4.w * scale;
#pragma unroll
        for (int j = 0; j < 4; j++) mx = fmaxf(mx, v[i * 4 + j]);
    }
#pragma unroll
    for (int o = 16; o; o >>= 1) mx = fmaxf(mx, __shfl_xor_sync(0xffffffffu, mx, o));

    float sum = 0.f;
#pragma unroll
    for (int i = 0; i < 16; i++) { v[i] = __expf(v[i] - mx); sum += v[i]; }
#pragma unroll
    for (int o = 16; o; o >>= 1) sum += __shfl_xor_sync(0xffffffffu, sum, o);
    const float inv = 1.f / sum;

#pragma unroll
    for (int i = 0; i < 4; i++) {
        const int col = i * 128 + lane * 4;
        *reinterpret_cast<__nv_bfloat162*>(q + col) =
            __floats2bfloat162_rn(v[i * 4 + 0] * inv, v[i * 4 + 1] * inv);
        *reinterpret_cast<__nv_bfloat162*>(q + col + 2) =
            __floats2bfloat162_rn(v[i * 4 + 2] * inv, v[i * 4 + 3] * inv);
    }
}

// ---------------------------------------------------------------------------
// Launcher. Inputs: x, batch(unused), Wq,bq, Wk,bk, Wv,bv, Wo,bo, beta.
// V projection runs on a second stream, overlapping scores+softmax; events
// fork/join so the graph capture records the dependency DAG.
// ---------------------------------------------------------------------------
extern "C" void kernel_launch(void* const* d_in, const int* in_sizes, int n_in,
                              void* d_out, int out_size)
{
    (void)in_sizes; (void)n_in; (void)out_size;
    const float* x    = (const float*)d_in[0];
    const float* Wq   = (const float*)d_in[2];
    const float* bq   = (const float*)d_in[3];
    const float* Wk   = (const float*)d_in[4];
    const float* bk   = (const float*)d_in[5];
    const float* Wv   = (const float*)d_in[6];
    const float* bv   = (const float*)d_in[7];
    const float* Wo   = (const float*)d_in[8];
    const float* bo   = (const float*)d_in[9];
    const float* beta = (const float*)d_in[10];
    float* out = (float*)d_out;

    __nv_bfloat16 *xb, *Wqb, *Wkb, *Wvb, *Wob, *Q, *K, *V, *P, *DYN;
    float *S;
    cudaGetSymbolAddress((void**)&xb,  g_xb);
    cudaGetSymbolAddress((void**)&Wqb, g_Wqb);
    cudaGetSymbolAddress((void**)&Wkb, g_Wkb);
    cudaGetSymbolAddress((void**)&Wvb, g_Wvb);
    cudaGetSymbolAddress((void**)&Wob, g_Wob);
    cudaGetSymbolAddress((void**)&Q,   g_Q);
    cudaGetSymbolAddress((void**)&K,   g_K);
    cudaGetSymbolAddress((void**)&V,   g_V);
    cudaGetSymbolAddress((void**)&S,   g_S);
    cudaGetSymbolAddress((void**)&P,   g_P);
    cudaGetSymbolAddress((void**)&DYN, g_DYN);

    static bool init_done = false;
    static cudaStream_t s2;
    static cudaEvent_t evFork, evV;
    if (!init_done) {
        cudaFuncSetAttribute(hgemm_qk,        cudaFuncAttributeMaxDynamicSharedMemorySize, SMEM_BYTES);
        cudaFuncSetAttribute(hgemm<0, false>, cudaFuncAttributeMaxDynamicSharedMemorySize, SMEM_BYTES);
        cudaFuncSetAttribute(hgemm<1, false>, cudaFuncAttributeMaxDynamicSharedMemorySize, SMEM_BYTES);
        cudaFuncSetAttribute(hgemm<2, true>,  cudaFuncAttributeMaxDynamicSharedMemorySize, SMEM_BYTES);
        cudaFuncSetAttribute(hgemm<3, false>, cudaFuncAttributeMaxDynamicSharedMemorySize, SMEM_BYTES);
        cudaStreamCreateWithFlags(&s2, cudaStreamNonBlocking);
        cudaEventCreateWithFlags(&evFork, cudaEventDisableTiming);
        cudaEventCreateWithFlags(&evV,    cudaEventDisableTiming);
        init_done = true;
    }

    const float scale = 1.0f / sqrtf((float)DIM);
    const dim3 blk(256);

    // converts (one launch, stream 0)
    {
        long total4 = ((long)NG * DIM + 4L * DIM * DIM) / 4;
        int blocks = (int)((total4 + 255) / 256);
        conv_all<<<blocks, 256>>>(x, Wq, Wk, Wv, Wo, xb, Wqb, Wkb, Wvb, Wob);
    }

    // fork: V projection on s2, concurrent with QK -> scores -> softmax
    cudaEventRecord(evFork, 0);
    cudaStreamWaitEvent(s2, evFork, 0);

    // s2: V = xb @ Wv^T + bv
    hgemm<0, false><<<dim3(6, 64, 1), blk, SMEM_BYTES, s2>>>(
        xb, Wvb, bv, V, DIM, DIM, DIM, DIM, 0, 0, 0, nullptr, nullptr);
    cudaEventRecord(evV, s2);

    // stream 0: Q, K projections (2-way fused)
    hgemm_qk<<<dim3(6, 64, 2), blk, SMEM_BYTES>>>(xb, Wqb, Wkb, bq, bk, Q, K);

    // stream 0: scores S_g = Q_g @ K_g^T (fp32, batched z=16)
    hgemm<1, false><<<dim3(4, 4, BGRP), blk, SMEM_BYTES>>>(
        Q, K, nullptr, S, DIM, DIM, DIM, GS,
        (long)GS * DIM, (long)GS * DIM, (long)GS * GS, nullptr, nullptr);

    // stream 0: masked softmax -> bf16 P
    softmax_rows<<<NG / 8, 256>>>(S, P, scale);

    // join: PV needs V
    cudaStreamWaitEvent(0, evV, 0);

    // stream 0: P @ V -> DYN (NN, batched z=16)
    hgemm<2, true><<<dim3(6, 4, BGRP), blk, SMEM_BYTES>>>(
        P, V, nullptr, DYN, GS, GS, DIM, DIM,
        (long)GS * GS, (long)GS * DIM, (long)GS * DIM, nullptr, nullptr);

    // stream 0: out = x + beta*(DYN @ Wo^T + bo)
    hgemm<3, false><<<dim3(6, 64, 1), blk, SMEM_BYTES>>>(
        DYN, Wob, bo, out, DIM, DIM, DIM, DIM, 0, 0, 0, x, beta);
}

// round 13
// speedup vs baseline: 1.0328x; 1.0328x over previous
#include <cuda_runtime.h>
#include <cuda_bf16.h>
#include <cstdint>
#include <cmath>

#define NG    8192
#define BGRP  16
#define GS    512
#define DIM   768

// tile sizes (proven config)
#define TBM 128
#define TBN 128
#define TBK 64
#define NSTAGE 3
#define STAGE_ELEMS (TBM * TBK)                   // 8192 bf16 per operand per stage
#define SMEM_BYTES (NSTAGE * 2 * STAGE_ELEMS * 2) // 98304 bytes

#if defined(__CUDA_ARCH__) && __CUDA_ARCH__ >= 900
#define GRID_DEP_SYNC() cudaGridDependencySynchronize()
#else
#define GRID_DEP_SYNC()
#endif

// ---------------- scratch (device globals; no allocs allowed) ----------------
__device__ __nv_bfloat16 g_xb [NG * DIM];
__device__ __nv_bfloat16 g_Wqb[DIM * DIM];
__device__ __nv_bfloat16 g_Wkb[DIM * DIM];
__device__ __nv_bfloat16 g_Wvb[DIM * DIM];
__device__ __nv_bfloat16 g_Wob[DIM * DIM];
__device__ __nv_bfloat16 g_Q  [NG * DIM];
__device__ __nv_bfloat16 g_K  [NG * DIM];
__device__ __nv_bfloat16 g_V  [NG * DIM];
__device__ float         g_S  [BGRP * GS * GS];
__device__ __nv_bfloat16 g_P  [BGRP * GS * GS];
__device__ __nv_bfloat16 g_DYN[NG * DIM];

// ---------------- helpers ----------------
__device__ __forceinline__ unsigned sptr(const void* p) {
    return (unsigned)__cvta_generic_to_shared(p);
}
__device__ __forceinline__ void cpasync16(unsigned s, const void* g) {
    asm volatile("cp.async.cg.shared.global [%0], [%1], 16;\n" :: "r"(s), "l"(g));
}
__device__ __forceinline__ void cp_commit() {
    asm volatile("cp.async.commit_group;\n" ::: "memory");
}
__device__ __forceinline__ void cp_wait1() {
    asm volatile("cp.async.wait_group 1;\n" ::: "memory");
}
__device__ __forceinline__ void ldsm4(unsigned& r0, unsigned& r1, unsigned& r2, unsigned& r3, unsigned a) {
    asm volatile("ldmatrix.sync.aligned.m8n8.x4.shared.b16 {%0,%1,%2,%3}, [%4];\n"
                 : "=r"(r0), "=r"(r1), "=r"(r2), "=r"(r3) : "r"(a));
}
__device__ __forceinline__ void ldsm4t(unsigned& r0, unsigned& r1, unsigned& r2, unsigned& r3, unsigned a) {
    asm volatile("ldmatrix.sync.aligned.m8n8.x4.trans.shared.b16 {%0,%1,%2,%3}, [%4];\n"
                 : "=r"(r0), "=r"(r1), "=r"(r2), "=r"(r3) : "r"(a));
}
__device__ __forceinline__ void mma16816(float* d, const unsigned* a, const unsigned* b) {
    asm volatile(
        "mma.sync.aligned.m16n8k16.row.col.f32.bf16.bf16.f32 "
        "{%0,%1,%2,%3}, {%4,%5,%6,%7}, {%8,%9}, {%0,%1,%2,%3};\n"
        : "+f"(d[0]), "+f"(d[1]), "+f"(d[2]), "+f"(d[3])
        : "r"(a[0]), "r"(a[1]), "r"(a[2]), "r"(a[3]), "r"(b[0]), "r"(b[1]));
}

// ---- cp.async tile issue into stage buffers (BK=64 -> 128B rows, 8-way XOR swizzle) ----
template<bool TB>
__device__ __forceinline__ void issue_tile(
    const __nv_bfloat16* __restrict__ A, const __nv_bfloat16* __restrict__ B,
    __nv_bfloat16* As, __nv_bfloat16* Bs,
    int row0, int col0, int lda, int ldb, int kt, int tid)
{
#pragma unroll
    for (int i = 0; i < 4; i++) {
        int lin = tid + i * 256;
        int r = lin >> 3, c = lin & 7;
        const __nv_bfloat16* g = A + (long)(row0 + r) * lda + kt * TBK + c * 8;
        cpasync16(sptr(As + r * TBK + ((c ^ (r & 7)) << 3)), g);
    }
    if (!TB) {
#pragma unroll
        for (int i = 0; i < 4; i++) {
            int lin = tid + i * 256;
            int r = lin >> 3, c = lin & 7;
            const __nv_bfloat16* g = B + (long)(col0 + r) * ldb + kt * TBK + c * 8;
            cpasync16(sptr(Bs + r * TBK + ((c ^ (r & 7)) << 3)), g);
        }
    } else {
#pragma unroll
        for (int i = 0; i < 4; i++) {
            int lin = tid + i * 256;
            int r = lin >> 4, c = lin & 15;
            const __nv_bfloat16* g = B + (long)(kt * TBK + r) * ldb + col0 + c * 8;
            cpasync16(sptr(Bs + r * TBN + ((c ^ (r & 7)) << 3)), g);
        }
    }
}

// ---------------------------------------------------------------------------
// Core bf16 tensor-core GEMM body (single-barrier 3-stage pipeline).
// MODE 0: bf16 C = acc + bias[col]
// MODE 1: fp32 C = acc
// MODE 2: bf16 C = acc
// MODE 3: fp32 C = X + beta[0]*(acc + bias[col])
// ---------------------------------------------------------------------------
template<int MODE, bool TB>
__device__ __forceinline__ void gemm_body(
    const __nv_bfloat16* __restrict__ A, const __nv_bfloat16* __restrict__ B,
    const float* __restrict__ bias, void* __restrict__ Cv,
    int K, int lda, int ldb, int ldc,
    const float* __restrict__ X, const float* __restrict__ beta,
    char* dsm, int row0, int col0)
{
    __nv_bfloat16* As = reinterpret_cast<__nv_bfloat16*>(dsm);
    __nv_bfloat16* Bs = As + NSTAGE * STAGE_ELEMS;

    const int tid  = threadIdx.x;
    const int lane = tid & 31;
    const int wid  = tid >> 5;
    const int wm   = (wid & 1) * 64;
    const int wn   = (wid >> 1) * 32;

    float acc[4][4][4];
#pragma unroll
    for (int i = 0; i < 4; i++)
#pragma unroll
        for (int j = 0; j < 4; j++)
#pragma unroll
            for (int k = 0; k < 4; k++) acc[i][j][k] = 0.f;

    const int ntiles = K / TBK;

    // wait for producer grid before first dependent load
    GRID_DEP_SYNC();

    issue_tile<TB>(A, B, As, Bs, row0, col0, lda, ldb, 0, tid);
    cp_commit();
    issue_tile<TB>(A, B, As + STAGE_ELEMS, Bs + STAGE_ELEMS, row0, col0, lda, ldb, 1, tid);
    cp_commit();

    for (int kt = 0; kt < ntiles; kt++) {
        const int stg = kt % NSTAGE;
        cp_wait1();
        __syncthreads();

        const __nv_bfloat16* Asb = As + stg * STAGE_ELEMS;
        const __nv_bfloat16* Bsb = Bs + stg * STAGE_ELEMS;

#pragma unroll
        for (int ks = 0; ks < 4; ks++) {
            unsigned aF[4][4], bF[4][2];
#pragma unroll
            for (int mi = 0; mi < 4; mi++) {
                int r = wm + mi * 16 + (lane & 15);
                int c = ks * 2 + (lane >> 4);
                ldsm4(aF[mi][0], aF[mi][1], aF[mi][2], aF[mi][3],
                      sptr(Asb + r * TBK + ((c ^ (r & 7)) << 3)));
            }
            if (!TB) {
#pragma unroll
                for (int nt = 0; nt < 2; nt++) {
                    int r = wn + nt * 16 + (lane & 15);
                    int c = ks * 2 + (lane >> 4);
                    unsigned r0, r1, r2, r3;
                    ldsm4(r0, r1, r2, r3,
                          sptr(Bsb + r * TBK + ((c ^ (r & 7)) << 3)));
                    bF[nt * 2 + 0][0] = r0; bF[nt * 2 + 0][1] = r2;
                    bF[nt * 2 + 1][0] = r1; bF[nt * 2 + 1][1] = r3;
                }
            } else {
#pragma unroll
                for (int nt = 0; nt < 2; nt++) {
                    int r = ks * 16 + (lane & 15);
                    int c = (wn >> 3) + nt * 2 + (lane >> 4);
                    unsigned r0, r1, r2, r3;
                    ldsm4t(r0, r1, r2, r3,
                           sptr(Bsb + r * TBN + ((c ^ (r & 7)) << 3)));
                    bF[nt * 2 + 0][0] = r0; bF[nt * 2 + 0][1] = r1;
                    bF[nt * 2 + 1][0] = r2; bF[nt * 2 + 1][1] = r3;
                }
            }
#pragma unroll
            for (int mi = 0; mi < 4; mi++)
#pragma unroll
                for (int nj = 0; nj < 4; nj++)
                    mma16816(acc[mi][nj], aF[mi], bF[nj]);
        }

        if (kt + 2 < ntiles) {
            const int ps = (kt + 2) % NSTAGE;
            issue_tile<TB>(A, B, As + ps * STAGE_ELEMS, Bs + ps * STAGE_ELEMS,
                           row0, col0, lda, ldb, kt + 2, tid);
        }
        cp_commit();
    }

    // ---------------- epilogue ----------------
    const int rg = lane >> 2;
    const int t  = lane & 3;
    float betav = 0.f;
    if (MODE == 3) betav = beta[0];

#pragma unroll
    for (int mi = 0; mi < 4; mi++) {
#pragma unroll
        for (int nj = 0; nj < 4; nj++) {
            const int r = row0 + wm + mi * 16 + rg;
            const int c = col0 + wn + nj * 8 + t * 2;
            const float d0 = acc[mi][nj][0];
            const float d1 = acc[mi][nj][1];
            const float d2 = acc[mi][nj][2];
            const float d3 = acc[mi][nj][3];

            if (MODE == 0) {
                __nv_bfloat16* C = reinterpret_cast<__nv_bfloat16*>(Cv);
                const float2 bb = *reinterpret_cast<const float2*>(bias + c);
                *reinterpret_cast<__nv_bfloat162*>(C + (long)r * ldc + c) =
                    __floats2bfloat162_rn(d0 + bb.x, d1 + bb.y);
                *reinterpret_cast<__nv_bfloat162*>(C + (long)(r + 8) * ldc + c) =
                    __floats2bfloat162_rn(d2 + bb.x, d3 + bb.y);
            } else if (MODE == 1) {
                float* C = reinterpret_cast<float*>(Cv);
                *reinterpret_cast<float2*>(C + (long)r * ldc + c) = make_float2(d0, d1);
                *reinterpret_cast<float2*>(C + (long)(r + 8) * ldc + c) = make_float2(d2, d3);
            } else if (MODE == 2) {
                __nv_bfloat16* C = reinterpret_cast<__nv_bfloat16*>(Cv);
                *reinterpret_cast<__nv_bfloat162*>(C + (long)r * ldc + c) =
                    __floats2bfloat162_rn(d0, d1);
                *reinterpret_cast<__nv_bfloat162*>(C + (long)(r + 8) * ldc + c) =
                    __floats2bfloat162_rn(d2, d3);
            } else {
                float* C = reinterpret_cast<float*>(Cv);
                const float2 bb = *reinterpret_cast<const float2*>(bias + c);
                const float2 x0 = *reinterpret_cast<const float2*>(X + (long)r * ldc + c);
                const float2 x1 = *reinterpret_cast<const float2*>(X + (long)(r + 8) * ldc + c);
                *reinterpret_cast<float2*>(C + (long)r * ldc + c) =
                    make_float2(x0.x + betav * (d0 + bb.x), x0.y + betav * (d1 + bb.y));
                *reinterpret_cast<float2*>(C + (long)(r + 8) * ldc + c) =
                    make_float2(x1.x + betav * (d2 + bb.x), x1.y + betav * (d3 + bb.y));
            }
        }
    }
}

// ---------------- QKV fused: grid.z in {0,1,2} selects W/bias/C ----------------
__global__ __launch_bounds__(256, 2)
void hgemm_qkv(const __nv_bfloat16* __restrict__ A,
               const __nv_bfloat16* __restrict__ W0, const __nv_bfloat16* __restrict__ W1,
               const __nv_bfloat16* __restrict__ W2,
               const float* __restrict__ b0, const float* __restrict__ b1,
               const float* __restrict__ b2,
               __nv_bfloat16* __restrict__ C0, __nv_bfloat16* __restrict__ C1,
               __nv_bfloat16* __restrict__ C2)
{
    extern __shared__ char dsm[];
    const int z = blockIdx.z;
    const __nv_bfloat16* W = (z == 0) ? W0 : (z == 1) ? W1 : W2;
    const float* bias      = (z == 0) ? b0 : (z == 1) ? b1 : b2;
    __nv_bfloat16* C       = (z == 0) ? C0 : (z == 1) ? C1 : C2;
    gemm_body<0, false>(A, W, bias, C, DIM, DIM, DIM, DIM, nullptr, nullptr,
                        dsm, blockIdx.y * TBM, blockIdx.x * TBN);
}

// ---------------- generic batched GEMM (z = group) ----------------
template<int MODE, bool TB>
__global__ __launch_bounds__(256, 2)
void hgemm(const __nv_bfloat16* __restrict__ A, const __nv_bfloat16* __restrict__ B,
           const float* __restrict__ bias, void* __restrict__ Cv,
           int K, int lda, int ldb, int ldc,
           long sA, long sB, long sC,
           const float* __restrict__ X, const float* __restrict__ beta)
{
    extern __shared__ char dsm[];
    const int bz = blockIdx.z;
    void* C;
    if (MODE == 1 || MODE == 3) C = (void*)((float*)Cv + bz * sC);
    else                        C = (void*)((__nv_bfloat16*)Cv + bz * sC);
    gemm_body<MODE, TB>(A + bz * sA, B + bz * sB, bias, C,
                        K, lda, ldb, ldc, X, beta,
                        dsm, blockIdx.y * TBM, blockIdx.x * TBN);
}

// ---------------- merged fp32 -> bf16 converts ----------------
__global__ __launch_bounds__(256)
void conv_all(const float* __restrict__ x,
              const float* __restrict__ wq, const float* __restrict__ wk,
              const float* __restrict__ wv, const float* __restrict__ wo,
              __nv_bfloat16* __restrict__ xb,
              __nv_bfloat16* __restrict__ wqb, __nv_bfloat16* __restrict__ wkb,
              __nv_bfloat16* __restrict__ wvb, __nv_bfloat16* __restrict__ wob)
{
    GRID_DEP_SYNC();
    const long NX = (long)NG * DIM;
    const long W  = (long)DIM * DIM;
    long i = ((long)blockIdx.x * 256 + threadIdx.x) * 4;
    if (i >= NX + 4 * W) return;
    const float* src;
    __nv_bfloat16* dst;
    long off;
    if (i < NX) { src = x; dst = xb; off = i; }
    else {
        long j = i - NX;
        int w = (int)(j / W);
        off = j - (long)w * W;
        src = (w == 0) ? wq : (w == 1) ? wk : (w == 2) ? wv : wo;
        dst = (w == 0) ? wqb : (w == 1) ? wkb : (w == 2) ? wvb : wob;
    }
    float4 v = *reinterpret_cast<const float4*>(src + off);
    *reinterpret_cast<__nv_bfloat162*>(dst + off)     = __floats2bfloat162_rn(v.x, v.y);
    *reinterpret_cast<__nv_bfloat162*>(dst + off + 2) = __floats2bfloat162_rn(v.z, v.w);
}

// ---------------- masked softmax (scale folded), warp-per-row ----------------
__global__ __launch_bounds__(256)
void softmax_rows(const float* __restrict__ S, __nv_bfloat16* __restrict__ P, float scale)
{
    GRID_DEP_SYNC();
    const int row  = blockIdx.x * 8 + (threadIdx.x >> 5);
    const int lane = threadIdx.x & 31;
    const int grp  = row >> 9;
    const int r    = row & 511;
    const float* p = S + ((long)grp << 18) + ((long)r << 9);
    __nv_bfloat16* q = P + ((long)grp << 18) + ((long)r << 9);

    float v[16];
    float mx = -INFINITY;
#pragma unroll
    for (int i = 0; i < 4; i++) {
        const int col = i * 128 + lane * 4;
        float4 v4 = *reinterpret_cast<const float4*>(p + col);
        v[i * 4 + 0] = (col + 0 == r) ? -INFINITY : v4.x * scale;
        v[i * 4 + 1] = (col + 1 == r) ? -INFINITY : v4.y * scale;
        v[i * 4 + 2] = (col + 2 == r) ? -INFINITY : v4.z * scale;
        v[i * 4 + 3] = (col + 3 == r) ? -INFINITY : v4.w * scale;
#pragma unroll
        for (int j = 0; j < 4; j++) mx = fmaxf(mx, v[i * 4 + j]);
    }
#pragma unroll
    for (int o = 16; o; o >>= 1) mx = fmaxf(mx, __shfl_xor_sync(0xffffffffu, mx, o));

    float sum = 0.f;
#pragma unroll
    for (int i = 0; i < 16; i++) { v[i] = __expf(v[i] - mx); sum += v[i]; }
#pragma unroll
    for (int o = 16; o; o >>= 1) sum += __shfl_xor_sync(0xffffffffu, sum, o);
    const float inv = 1.f / sum;

#pragma unroll
    for (int i = 0; i < 4; i++) {
        const int col = i * 128 + lane * 4;
        *reinterpret_cast<__nv_bfloat162*>(q + col) =
            __floats2bfloat162_rn(v[i * 4 + 0] * inv, v[i * 4 + 1] * inv);
        *reinterpret_cast<__nv_bfloat162*>(q + col + 2) =
            __floats2bfloat162_rn(v[i * 4 + 2] * inv, v[i * 4 + 3] * inv);
    }
}

// ---------------------------------------------------------------------------
// Launcher. Inputs: x, batch(unused), Wq,bq, Wk,bk, Wv,bv, Wo,bo, beta.
// All launches carry the PDL (programmatic stream serialization) attribute so
// successor grids launch/prologue while the predecessor drains.
// ---------------------------------------------------------------------------
extern "C" void kernel_launch(void* const* d_in, const int* in_sizes, int n_in,
                              void* d_out, int out_size)
{
    (void)in_sizes; (void)n_in; (void)out_size;
    const float* x    = (const float*)d_in[0];
    const float* Wq   = (const float*)d_in[2];
    const float* bq   = (const float*)d_in[3];
    const float* Wk   = (const float*)d_in[4];
    const float* bk   = (const float*)d_in[5];
    const float* Wv   = (const float*)d_in[6];
    const float* bv   = (const float*)d_in[7];
    const float* Wo   = (const float*)d_in[8];
    const float* bo   = (const float*)d_in[9];
    const float* beta = (const float*)d_in[10];
    float* out = (float*)d_out;

    __nv_bfloat16 *xb, *Wqb, *Wkb, *Wvb, *Wob, *Q, *K, *V, *P, *DYN;
    float *S;
    cudaGetSymbolAddress((void**)&xb,  g_xb);
    cudaGetSymbolAddress((void**)&Wqb, g_Wqb);
    cudaGetSymbolAddress((void**)&Wkb, g_Wkb);
    cudaGetSymbolAddress((void**)&Wvb, g_Wvb);
    cudaGetSymbolAddress((void**)&Wob, g_Wob);
    cudaGetSymbolAddress((void**)&Q,   g_Q);
    cudaGetSymbolAddress((void**)&K,   g_K);
    cudaGetSymbolAddress((void**)&V,   g_V);
    cudaGetSymbolAddress((void**)&S,   g_S);
    cudaGetSymbolAddress((void**)&P,   g_P);
    cudaGetSymbolAddress((void**)&DYN, g_DYN);

    static bool init_done = false;
    if (!init_done) {
        cudaFuncSetAttribute(hgemm_qkv,       cudaFuncAttributeMaxDynamicSharedMemorySize, SMEM_BYTES);
        cudaFuncSetAttribute(hgemm<1, false>, cudaFuncAttributeMaxDynamicSharedMemorySize, SMEM_BYTES);
        cudaFuncSetAttribute(hgemm<2, true>,  cudaFuncAttributeMaxDynamicSharedMemorySize, SMEM_BYTES);
        cudaFuncSetAttribute(hgemm<3, false>, cudaFuncAttributeMaxDynamicSharedMemorySize, SMEM_BYTES);
        init_done = true;
    }

    const float scale = 1.0f / sqrtf((float)DIM);

    cudaLaunchAttribute pdl[1];
    pdl[0].id = cudaLaunchAttributeProgrammaticStreamSerialization;
    pdl[0].val.programmaticStreamSerializationAllowed = 1;

    auto mkcfg = [&](dim3 g, dim3 b, size_t sm) {
        cudaLaunchConfig_t cfg{};
        cfg.gridDim = g;
        cfg.blockDim = b;
        cfg.dynamicSmemBytes = sm;
        cfg.stream = 0;
        cfg.attrs = pdl;
        cfg.numAttrs = 1;
        return cfg;
    };

    // converts (one launch)
    {
        long total4 = ((long)NG * DIM + 4L * DIM * DIM) / 4;
        int blocks = (int)((total4 + 255) / 256);
        cudaLaunchConfig_t cfg = mkcfg(dim3(blocks), dim3(256), 0);
        cudaLaunchKernelEx(&cfg, conv_all, x, Wq, Wk, Wv, Wo, xb, Wqb, Wkb, Wvb, Wob);
    }

    // Q/K/V projections in one launch
    {
        cudaLaunchConfig_t cfg = mkcfg(dim3(6, 64, 3), dim3(256), SMEM_BYTES);
        cudaLaunchKernelEx(&cfg, hgemm_qkv, (const __nv_bfloat16*)xb,
                           (const __nv_bfloat16*)Wqb, (const __nv_bfloat16*)Wkb,
                           (const __nv_bfloat16*)Wvb, bq, bk, bv, Q, K, V);
    }

    // scores: S_g = Q_g @ K_g^T (fp32, batched z=16)
    {
        cudaLaunchConfig_t cfg = mkcfg(dim3(4, 4, BGRP), dim3(256), SMEM_BYTES);
        cudaLaunchKernelEx(&cfg, hgemm<1, false>,
                           (const __nv_bfloat16*)Q, (const __nv_bfloat16*)K,
                           (const float*)nullptr, (void*)S,
                           DIM, DIM, DIM, GS,
                           (long)GS * DIM, (long)GS * DIM, (long)GS * GS,
                           (const float*)nullptr, (const float*)nullptr);
    }

    // masked softmax -> bf16 P
    {
        cudaLaunchConfig_t cfg = mkcfg(dim3(NG / 8), dim3(256), 0);
        cudaLaunchKernelEx(&cfg, softmax_rows, (const float*)S, P, scale);
    }

    // P @ V -> DYN (NN, batched z=16)
    {
        cudaLaunchConfig_t cfg = mkcfg(dim3(6, 4, BGRP), dim3(256), SMEM_BYTES);
        cudaLaunchKernelEx(&cfg, hgemm<2, true>,
                           (const __nv_bfloat16*)P, (const __nv_bfloat16*)V,
                           (const float*)nullptr, (void*)DYN,
                           GS, GS, DIM, DIM,
                           (long)GS * GS, (long)GS * DIM, (long)GS * DIM,
                           (const float*)nullptr, (const float*)nullptr);
    }

    // out = x + beta*(DYN @ Wo^T + bo)
    {
        cudaLaunchConfig_t cfg = mkcfg(dim3(6, 64, 1), dim3(256), SMEM_BYTES);
        cudaLaunchKernelEx(&cfg, hgemm<3, false>,
                           (const __nv_bfloat16*)DYN, (const __nv_bfloat16*)Wob,
                           bo, (void*)out,
                           DIM, DIM, DIM, DIM, 0L, 0L, 0L,
                           x, beta);
    }
}

// round 14
// speedup vs baseline: 1.0330x; 1.0002x over previous
#include <cuda_runtime.h>
#include <cuda_bf16.h>
#include <cstdint>
#include <cmath>

#define NG    8192
#define BGRP  16
#define GS    512
#define DIM   768

// tile sizes (proven config)
#define TBM 128
#define TBN 128
#define TBK 64
#define NSTAGE 3
#define STAGE_ELEMS (TBM * TBK)                   // 8192 bf16 per operand per stage
#define SMEM_BYTES (NSTAGE * 2 * STAGE_ELEMS * 2) // 98304 bytes

#define SCALE_CONST 0.03608439182435161f          // 1/sqrt(768)

#if defined(__CUDA_ARCH__) && __CUDA_ARCH__ >= 900
#define GRID_DEP_SYNC() cudaGridDependencySynchronize()
#else
#define GRID_DEP_SYNC()
#endif

// ---------------- scratch (device globals; no allocs allowed) ----------------
__device__ __nv_bfloat16 g_xb [NG * DIM];
__device__ __nv_bfloat16 g_Wqb[DIM * DIM];
__device__ __nv_bfloat16 g_Wkb[DIM * DIM];
__device__ __nv_bfloat16 g_Wvb[DIM * DIM];
__device__ __nv_bfloat16 g_Wob[DIM * DIM];
__device__ __nv_bfloat16 g_Q  [NG * DIM];
__device__ __nv_bfloat16 g_K  [NG * DIM];
__device__ __nv_bfloat16 g_V  [NG * DIM];
__device__ __nv_bfloat16 g_P  [BGRP * GS * GS];   // unnormalized exp-scores, bf16
__device__ float         g_rs [NG];               // per-row exp sums
__device__ __nv_bfloat16 g_DYN[NG * DIM];

// ---------------- helpers ----------------
__device__ __forceinline__ unsigned sptr(const void* p) {
    return (unsigned)__cvta_generic_to_shared(p);
}
__device__ __forceinline__ void cpasync16(unsigned s, const void* g) {
    asm volatile("cp.async.cg.shared.global [%0], [%1], 16;\n" :: "r"(s), "l"(g));
}
__device__ __forceinline__ void cp_commit() {
    asm volatile("cp.async.commit_group;\n" ::: "memory");
}
__device__ __forceinline__ void cp_wait1() {
    asm volatile("cp.async.wait_group 1;\n" ::: "memory");
}
__device__ __forceinline__ void ldsm4(unsigned& r0, unsigned& r1, unsigned& r2, unsigned& r3, unsigned a) {
    asm volatile("ldmatrix.sync.aligned.m8n8.x4.shared.b16 {%0,%1,%2,%3}, [%4];\n"
                 : "=r"(r0), "=r"(r1), "=r"(r2), "=r"(r3) : "r"(a));
}
__device__ __forceinline__ void ldsm4t(unsigned& r0, unsigned& r1, unsigned& r2, unsigned& r3, unsigned a) {
    asm volatile("ldmatrix.sync.aligned.m8n8.x4.trans.shared.b16 {%0,%1,%2,%3}, [%4];\n"
                 : "=r"(r0), "=r"(r1), "=r"(r2), "=r"(r3) : "r"(a));
}
__device__ __forceinline__ void mma16816(float* d, const unsigned* a, const unsigned* b) {
    asm volatile(
        "mma.sync.aligned.m16n8k16.row.col.f32.bf16.bf16.f32 "
        "{%0,%1,%2,%3}, {%4,%5,%6,%7}, {%8,%9}, {%0,%1,%2,%3};\n"
        : "+f"(d[0]), "+f"(d[1]), "+f"(d[2]), "+f"(d[3])
        : "r"(a[0]), "r"(a[1]), "r"(a[2]), "r"(a[3]), "r"(b[0]), "r"(b[1]));
}

// ---- cp.async tile issue into stage buffers (BK=64 -> 128B rows, 8-way XOR swizzle) ----
template<bool TB>
__device__ __forceinline__ void issue_tile(
    const __nv_bfloat16* __restrict__ A, const __nv_bfloat16* __restrict__ B,
    __nv_bfloat16* As, __nv_bfloat16* Bs,
    int row0, int col0, int lda, int ldb, int kt, int tid)
{
#pragma unroll
    for (int i = 0; i < 4; i++) {
        int lin = tid + i * 256;
        int r = lin >> 3, c = lin & 7;
        const __nv_bfloat16* g = A + (long)(row0 + r) * lda + kt * TBK + c * 8;
        cpasync16(sptr(As + r * TBK + ((c ^ (r & 7)) << 3)), g);
    }
    if (!TB) {
#pragma unroll
        for (int i = 0; i < 4; i++) {
            int lin = tid + i * 256;
            int r = lin >> 3, c = lin & 7;
            const __nv_bfloat16* g = B + (long)(col0 + r) * ldb + kt * TBK + c * 8;
            cpasync16(sptr(Bs + r * TBK + ((c ^ (r & 7)) << 3)), g);
        }
    } else {
#pragma unroll
        for (int i = 0; i < 4; i++) {
            int lin = tid + i * 256;
            int r = lin >> 4, c = lin & 15;
            const __nv_bfloat16* g = B + (long)(kt * TBK + r) * ldb + col0 + c * 8;
            cpasync16(sptr(Bs + r * TBN + ((c ^ (r & 7)) << 3)), g);
        }
    }
}

// ---------------------------------------------------------------------------
// Core bf16 tensor-core GEMM body (single-barrier 3-stage pipeline).
// MODE 0: bf16 C = acc + bias[col]                      (QKV projections)
// MODE 1: bf16 C = exp(acc*scale) diag-masked; row sums atomically added to
//         rowsum (= bias ptr, non-const)                (fused scores+exp)
// MODE 2: bf16 C = acc * (1/rowsum[row])  (rowsum = bias ptr)   (PV + norm)
// MODE 3: fp32 C = X + beta[0]*(acc + bias[col])        (out-proj + residual)
// ---------------------------------------------------------------------------
template<int MODE, bool TB>
__device__ __forceinline__ void gemm_body(
    const __nv_bfloat16* __restrict__ A, const __nv_bfloat16* __restrict__ B,
    const float* __restrict__ bias, void* __restrict__ Cv,
    int K, int lda, int ldb, int ldc,
    const float* __restrict__ X, const float* __restrict__ beta,
    char* dsm, int row0, int col0)
{
    __nv_bfloat16* As = reinterpret_cast<__nv_bfloat16*>(dsm);
    __nv_bfloat16* Bs = As + NSTAGE * STAGE_ELEMS;

    const int tid  = threadIdx.x;
    const int lane = tid & 31;
    const int wid  = tid >> 5;
    const int wm   = (wid & 1) * 64;
    const int wn   = (wid >> 1) * 32;

    float acc[4][4][4];
#pragma unroll
    for (int i = 0; i < 4; i++)
#pragma unroll
        for (int j = 0; j < 4; j++)
#pragma unroll
            for (int k = 0; k < 4; k++) acc[i][j][k] = 0.f;

    const int ntiles = K / TBK;

    GRID_DEP_SYNC();

    issue_tile<TB>(A, B, As, Bs, row0, col0, lda, ldb, 0, tid);
    cp_commit();
    issue_tile<TB>(A, B, As + STAGE_ELEMS, Bs + STAGE_ELEMS, row0, col0, lda, ldb, 1, tid);
    cp_commit();

    for (int kt = 0; kt < ntiles; kt++) {
        const int stg = kt % NSTAGE;
        cp_wait1();
        __syncthreads();

        const __nv_bfloat16* Asb = As + stg * STAGE_ELEMS;
        const __nv_bfloat16* Bsb = Bs + stg * STAGE_ELEMS;

#pragma unroll
        for (int ks = 0; ks < 4; ks++) {
            unsigned aF[4][4], bF[4][2];
#pragma unroll
            for (int mi = 0; mi < 4; mi++) {
                int r = wm + mi * 16 + (lane & 15);
                int c = ks * 2 + (lane >> 4);
                ldsm4(aF[mi][0], aF[mi][1], aF[mi][2], aF[mi][3],
                      sptr(Asb + r * TBK + ((c ^ (r & 7)) << 3)));
            }
            if (!TB) {
#pragma unroll
                for (int nt = 0; nt < 2; nt++) {
                    int r = wn + nt * 16 + (lane & 15);
                    int c = ks * 2 + (lane >> 4);
                    unsigned r0, r1, r2, r3;
                    ldsm4(r0, r1, r2, r3,
                          sptr(Bsb + r * TBK + ((c ^ (r & 7)) << 3)));
                    bF[nt * 2 + 0][0] = r0; bF[nt * 2 + 0][1] = r2;
                    bF[nt * 2 + 1][0] = r1; bF[nt * 2 + 1][1] = r3;
                }
            } else {
#pragma unroll
                for (int nt = 0; nt < 2; nt++) {
                    int r = ks * 16 + (lane & 15);
                    int c = (wn >> 3) + nt * 2 + (lane >> 4);
                    unsigned r0, r1, r2, r3;
                    ldsm4t(r0, r1, r2, r3,
                           sptr(Bsb + r * TBN + ((c ^ (r & 7)) << 3)));
                    bF[nt * 2 + 0][0] = r0; bF[nt * 2 + 0][1] = r1;
                    bF[nt * 2 + 1][0] = r2; bF[nt * 2 + 1][1] = r3;
                }
            }
#pragma unroll
            for (int mi = 0; mi < 4; mi++)
#pragma unroll
                for (int nj = 0; nj < 4; nj++)
                    mma16816(acc[mi][nj], aF[mi], bF[nj]);
        }

        if (kt + 2 < ntiles) {
            const int ps = (kt + 2) % NSTAGE;
            issue_tile<TB>(A, B, As + ps * STAGE_ELEMS, Bs + ps * STAGE_ELEMS,
                           row0, col0, lda, ldb, kt + 2, tid);
        }
        cp_commit();
    }

    // ---------------- epilogue ----------------
    const int rg = lane >> 2;
    const int t  = lane & 3;
    float betav = 0.f;
    if (MODE == 3) betav = beta[0];

    float rsum[4][2];
    if (MODE == 1) {
#pragma unroll
        for (int i = 0; i < 4; i++) { rsum[i][0] = 0.f; rsum[i][1] = 0.f; }
    }

#pragma unroll
    for (int mi = 0; mi < 4; mi++) {
#pragma unroll
        for (int nj = 0; nj < 4; nj++) {
            const int r = row0 + wm + mi * 16 + rg;
            const int c = col0 + wn + nj * 8 + t * 2;
            const float d0 = acc[mi][nj][0];
            const float d1 = acc[mi][nj][1];
            const float d2 = acc[mi][nj][2];
            const float d3 = acc[mi][nj][3];

            if (MODE == 0) {
                __nv_bfloat16* C = reinterpret_cast<__nv_bfloat16*>(Cv);
                const float2 bb = *reinterpret_cast<const float2*>(bias + c);
                *reinterpret_cast<__nv_bfloat162*>(C + (long)r * ldc + c) =
                    __floats2bfloat162_rn(d0 + bb.x, d1 + bb.y);
                *reinterpret_cast<__nv_bfloat162*>(C + (long)(r + 8) * ldc + c) =
                    __floats2bfloat162_rn(d2 + bb.x, d3 + bb.y);
            } else if (MODE == 1) {
                // e = exp(scale*s), diagonal masked to 0 (row/col are group-local)
                __nv_bfloat16* C = reinterpret_cast<__nv_bfloat16*>(Cv);
                float e0 = (r     == c    ) ? 0.f : __expf(d0 * SCALE_CONST);
                float e1 = (r     == c + 1) ? 0.f : __expf(d1 * SCALE_CONST);
                float e2 = (r + 8 == c    ) ? 0.f : __expf(d2 * SCALE_CONST);
                float e3 = (r + 8 == c + 1) ? 0.f : __expf(d3 * SCALE_CONST);
                *reinterpret_cast<__nv_bfloat162*>(C + (long)r * ldc + c) =
                    __floats2bfloat162_rn(e0, e1);
                *reinterpret_cast<__nv_bfloat162*>(C + (long)(r + 8) * ldc + c) =
                    __floats2bfloat162_rn(e2, e3);
                rsum[mi][0] += e0 + e1;
                rsum[mi][1] += e2 + e3;
            } else if (MODE == 2) {
                __nv_bfloat16* C = reinterpret_cast<__nv_bfloat16*>(Cv);
                const float inv0 = 1.f / bias[r];
                const float inv1 = 1.f / bias[r + 8];
                *reinterpret_cast<__nv_bfloat162*>(C + (long)r * ldc + c) =
                    __floats2bfloat162_rn(d0 * inv0, d1 * inv0);
                *reinterpret_cast<__nv_bfloat162*>(C + (long)(r + 8) * ldc + c) =
                    __floats2bfloat162_rn(d2 * inv1, d3 * inv1);
            } else {
                float* C = reinterpret_cast<float*>(Cv);
                const float2 bb = *reinterpret_cast<const float2*>(bias + c);
                const float2 x0 = *reinterpret_cast<const float2*>(X + (long)r * ldc + c);
                const float2 x1 = *reinterpret_cast<const float2*>(X + (long)(r + 8) * ldc + c);
                *reinterpret_cast<float2*>(C + (long)r * ldc + c) =
                    make_float2(x0.x + betav * (d0 + bb.x), x0.y + betav * (d1 + bb.y));
                *reinterpret_cast<float2*>(C + (long)(r + 8) * ldc + c) =
                    make_float2(x1.x + betav * (d2 + bb.x), x1.y + betav * (d3 + bb.y));
            }
        }
    }

    if (MODE == 1) {
        // reduce 32-col partial sums across the 4 t-lanes, then one atomic per row
        float* rs = const_cast<float*>(bias);
#pragma unroll
        for (int mi = 0; mi < 4; mi++) {
            float s0 = rsum[mi][0], s1 = rsum[mi][1];
            s0 += __shfl_xor_sync(0xffffffffu, s0, 1);
            s0 += __shfl_xor_sync(0xffffffffu, s0, 2);
            s1 += __shfl_xor_sync(0xffffffffu, s1, 1);
            s1 += __shfl_xor_sync(0xffffffffu, s1, 2);
            if (t == 0) {
                const int r = row0 + wm + mi * 16 + rg;
                atomicAdd(rs + r, s0);
                atomicAdd(rs + r + 8, s1);
            }
        }
    }
}

// ---------------- QKV fused: grid.z in {0,1,2} selects W/bias/C ----------------
__global__ __launch_bounds__(256, 2)
void hgemm_qkv(const __nv_bfloat16* __restrict__ A,
               const __nv_bfloat16* __restrict__ W0, const __nv_bfloat16* __restrict__ W1,
               const __nv_bfloat16* __restrict__ W2,
               const float* __restrict__ b0, const float* __restrict__ b1,
               const float* __restrict__ b2,
               __nv_bfloat16* __restrict__ C0, __nv_bfloat16* __restrict__ C1,
               __nv_bfloat16* __restrict__ C2)
{
    extern __shared__ char dsm[];
    const int z = blockIdx.z;
    const __nv_bfloat16* W = (z == 0) ? W0 : (z == 1) ? W1 : W2;
    const float* bias      = (z == 0) ? b0 : (z == 1) ? b1 : b2;
    __nv_bfloat16* C       = (z == 0) ? C0 : (z == 1) ? C1 : C2;
    gemm_body<0, false>(A, W, bias, C, DIM, DIM, DIM, DIM, nullptr, nullptr,
                        dsm, blockIdx.y * TBM, blockIdx.x * TBN);
}

// ---------------- generic batched GEMM (z = group) ----------------
// For MODE 1/2, `bias` carries the rowsum array (offset per group inside).
template<int MODE, bool TB>
__global__ __launch_bounds__(256, 2)
void hgemm(const __nv_bfloat16* __restrict__ A, const __nv_bfloat16* __restrict__ B,
           const float* __restrict__ bias, void* __restrict__ Cv,
           int K, int lda, int ldb, int ldc,
           long sA, long sB, long sC,
           const float* __restrict__ X, const float* __restrict__ beta)
{
    extern __shared__ char dsm[];
    const int bz = blockIdx.z;
    void* C;
    if (MODE == 3) C = (void*)((float*)Cv + bz * sC);
    else           C = (void*)((__nv_bfloat16*)Cv + bz * sC);
    const float* b = (MODE == 1 || MODE == 2) ? bias + (long)bz * GS : bias;
    gemm_body<MODE, TB>(A + bz * sA, B + bz * sB, b, C,
                        K, lda, ldb, ldc, X, beta,
                        dsm, blockIdx.y * TBM, blockIdx.x * TBN);
}

// ---------------- merged fp32 -> bf16 converts + rowsum zeroing ----------------
__global__ __launch_bounds__(256)
void conv_all(const float* __restrict__ x,
              const float* __restrict__ wq, const float* __restrict__ wk,
              const float* __restrict__ wv, const float* __restrict__ wo,
              __nv_bfloat16* __restrict__ xb,
              __nv_bfloat16* __restrict__ wqb, __nv_bfloat16* __restrict__ wkb,
              __nv_bfloat16* __restrict__ wvb, __nv_bfloat16* __restrict__ wob,
              float* __restrict__ rowsum)
{
    GRID_DEP_SYNC();
    long gid = (long)blockIdx.x * 256 + threadIdx.x;
    if (gid < NG) rowsum[gid] = 0.f;

    const long NX = (long)NG * DIM;
    const long W  = (long)DIM * DIM;
    long i = gid * 4;
    if (i >= NX + 4 * W) return;
    const float* src;
    __nv_bfloat16* dst;
    long off;
    if (i < NX) { src = x; dst = xb; off = i; }
    else {
        long j = i - NX;
        int w = (int)(j / W);
        off = j - (long)w * W;
        src = (w == 0) ? wq : (w == 1) ? wk : (w == 2) ? wv : wo;
        dst = (w == 0) ? wqb : (w == 1) ? wkb : (w == 2) ? wvb : wob;
    }
    float4 v = *reinterpret_cast<const float4*>(src + off);
    *reinterpret_cast<__nv_bfloat162*>(dst + off)     = __floats2bfloat162_rn(v.x, v.y);
    *reinterpret_cast<__nv_bfloat162*>(dst + off + 2) = __floats2bfloat162_rn(v.z, v.w);
}

// ---------------------------------------------------------------------------
// Launcher. Inputs: x, batch(unused), Wq,bq, Wk,bk, Wv,bv, Wo,bo, beta.
// 5 kernels, all PDL-linked:
//   conv_all -> QKV -> scores(exp+rowsum) -> PV(normalize) -> out-proj
// ---------------------------------------------------------------------------
extern "C" void kernel_launch(void* const* d_in, const int* in_sizes, int n_in,
                              void* d_out, int out_size)
{
    (void)in_sizes; (void)n_in; (void)out_size;
    const float* x    = (const float*)d_in[0];
    const float* Wq   = (const float*)d_in[2];
    const float* bq   = (const float*)d_in[3];
    const float* Wk   = (const float*)d_in[4];
    const float* bk   = (const float*)d_in[5];
    const float* Wv   = (const float*)d_in[6];
    const float* bv   = (const float*)d_in[7];
    const float* Wo   = (const float*)d_in[8];
    const float* bo   = (const float*)d_in[9];
    const float* beta = (const float*)d_in[10];
    float* out = (float*)d_out;

    __nv_bfloat16 *xb, *Wqb, *Wkb, *Wvb, *Wob, *Q, *K, *V, *P, *DYN;
    float *RS;
    cudaGetSymbolAddress((void**)&xb,  g_xb);
    cudaGetSymbolAddress((void**)&Wqb, g_Wqb);
    cudaGetSymbolAddress((void**)&Wkb, g_Wkb);
    cudaGetSymbolAddress((void**)&Wvb, g_Wvb);
    cudaGetSymbolAddress((void**)&Wob, g_Wob);
    cudaGetSymbolAddress((void**)&Q,   g_Q);
    cudaGetSymbolAddress((void**)&K,   g_K);
    cudaGetSymbolAddress((void**)&V,   g_V);
    cudaGetSymbolAddress((void**)&P,   g_P);
    cudaGetSymbolAddress((void**)&RS,  g_rs);
    cudaGetSymbolAddress((void**)&DYN, g_DYN);

    static bool init_done = false;
    if (!init_done) {
        cudaFuncSetAttribute(hgemm_qkv,       cudaFuncAttributeMaxDynamicSharedMemorySize, SMEM_BYTES);
        cudaFuncSetAttribute(hgemm<1, false>, cudaFuncAttributeMaxDynamicSharedMemorySize, SMEM_BYTES);
        cudaFuncSetAttribute(hgemm<2, true>,  cudaFuncAttributeMaxDynamicSharedMemorySize, SMEM_BYTES);
        cudaFuncSetAttribute(hgemm<3, false>, cudaFuncAttributeMaxDynamicSharedMemorySize, SMEM_BYTES);
        init_done = true;
    }

    cudaLaunchAttribute pdl[1];
    pdl[0].id = cudaLaunchAttributeProgrammaticStreamSerialization;
    pdl[0].val.programmaticStreamSerializationAllowed = 1;

    auto mkcfg = [&](dim3 g, dim3 b, size_t sm) {
        cudaLaunchConfig_t cfg{};
        cfg.gridDim = g;
        cfg.blockDim = b;
        cfg.dynamicSmemBytes = sm;
        cfg.stream = 0;
        cfg.attrs = pdl;
        cfg.numAttrs = 1;
        return cfg;
    };

    // converts + rowsum zero (one launch)
    {
        long total4 = ((long)NG * DIM + 4L * DIM * DIM) / 4;
        int blocks = (int)((total4 + 255) / 256);
        cudaLaunchConfig_t cfg = mkcfg(dim3(blocks), dim3(256), 0);
        cudaLaunchKernelEx(&cfg, conv_all, x, Wq, Wk, Wv, Wo,
                           xb, Wqb, Wkb, Wvb, Wob, RS);
    }

    // Q/K/V projections in one launch
    {
        cudaLaunchConfig_t cfg = mkcfg(dim3(6, 64, 3), dim3(256), SMEM_BYTES);
        cudaLaunchKernelEx(&cfg, hgemm_qkv, (const __nv_bfloat16*)xb,
                           (const __nv_bfloat16*)Wqb, (const __nv_bfloat16*)Wkb,
                           (const __nv_bfloat16*)Wvb, bq, bk, bv, Q, K, V);
    }

    // fused scores+exp+rowsum: P_g = exp(scale * Q_g K_g^T) masked, bf16
    {
        cudaLaunchConfig_t cfg = mkcfg(dim3(4, 4, BGRP), dim3(256), SMEM_BYTES);
        cudaLaunchKernelEx(&cfg, hgemm<1, false>,
                           (const __nv_bfloat16*)Q, (const __nv_bfloat16*)K,
                           (const float*)RS, (void*)P,
                           DIM, DIM, DIM, GS,
                           (long)GS * DIM, (long)GS * DIM, (long)GS * GS,
                           (const float*)nullptr, (const float*)nullptr);
    }

    // PV + normalization: DYN_g = (P_g @ V_g) / rowsum
    {
        cudaLaunchConfig_t cfg = mkcfg(dim3(6, 4, BGRP), dim3(256), SMEM_BYTES);
        cudaLaunchKernelEx(&cfg, hgemm<2, true>,
                           (const __nv_bfloat16*)P, (const __nv_bfloat16*)V,
                           (const float*)RS, (void*)DYN,
                           GS, GS, DIM, DIM,
                           (long)GS * GS, (long)GS * DIM, (long)GS * DIM,
                           (const float*)nullptr, (const float*)nullptr);
    }

    // out = x + beta*(DYN @ Wo^T + bo)
    {
        cudaLaunchConfig_t cfg = mkcfg(dim3(6, 64, 1), dim3(256), SMEM_BYTES);
        cudaLaunchKernelEx(&cfg, hgemm<3, false>,
                           (const __nv_bfloat16*)DYN, (const __nv_bfloat16*)Wob,
                           bo, (void*)out,
                           DIM, DIM, DIM, DIM, 0L, 0L, 0L,
                           x, beta);
    }
}